// round 6
// baseline (speedup 1.0000x reference)
#include <cuda_runtime.h>
#include <cuda_bf16.h>
#include <math.h>

typedef unsigned long long ull;
#define FMA2(acc, a, b) asm("fma.rn.f32x2 %0, %1, %2, %0;" : "+l"(acc) : "l"(a), "l"(b))
__device__ __forceinline__ ull dupf(float x) { ull r; asm("mov.b64 %0, {%1, %1};" : "=l"(r) : "f"(x)); return r; }
__device__ __forceinline__ float2 u2f(ull v) { float2 r; asm("mov.b64 {%0, %1}, %2;" : "=f"(r.x), "=f"(r.y) : "l"(v)); return r; }

// device-global scratch (allocation-free)
__device__ float g_XW [(size_t)4096 * 4096];   // 64MB
__device__ float g_H  [(size_t)4096 * 1024];   // 16MB
__device__ float g_Up0[(size_t)1024 * 4096];   // gate-interleaved U0
__device__ float g_Up1[(size_t)1024 * 4096];
__device__ float g_Zp [4 * 16 * 4096];         // k-split partials
__device__ float g_h  [2][16 * 1024];          // double-buffered h
__device__ unsigned g_cnt, g_gen;

// Up[k][j][g] = U[k][g*1024+j]
__global__ void repack(const float* __restrict__ U, float* __restrict__ Up) {
    int i = blockIdx.x * 256 + threadIdx.x;        // 0..1M-1
    int k = i >> 10, j = i & 1023;
    float4 v = { U[(size_t)k*4096 + j],        U[(size_t)k*4096 + 1024 + j],
                 U[(size_t)k*4096 + 2048 + j], U[(size_t)k*4096 + 3072 + j] };
    ((float4*)Up)[(size_t)k*1024 + j] = v;
}

// C[4096,N] = A @ Bm[1024,N] + bias.  128x128x16 tiles, 8x8/thr via f32x2.
// amode1: row s <- emb[seq[s%16, s/16]]*32.  cmode1: out[(s%16)*256 + s/16].
__global__ __launch_bounds__(256, 2)
void gemm(const float* __restrict__ A, const float* __restrict__ Bm,
          const float* __restrict__ bias, float* __restrict__ C,
          int N, int amode, int cmode,
          const int* __restrict__ seq, const float* __restrict__ emb)
{
    __shared__ float As[16][128];
    __shared__ float Bs[16][128];
    int tid = threadIdx.x;
    int m0 = blockIdx.y * 128, n0 = blockIdx.x * 128;
    int ty = tid >> 4, tx = tid & 15;
    ull acc[8][4];
#pragma unroll
    for (int i = 0; i < 8; i++)
#pragma unroll
        for (int j = 0; j < 4; j++) acc[i][j] = 0ull;

    for (int k0 = 0; k0 < 1024; k0 += 16) {
#pragma unroll
        for (int i = 0; i < 2; i++) {                       // A tile, transposed
            int q = tid + i * 256, row = q >> 2, kc = (q & 3) * 4, s = m0 + row;
            float4 v;
            if (amode) {
                int tok = seq[(s & 15) * 256 + (s >> 4)];
                v = *(const float4*)(emb + (size_t)tok * 1024 + k0 + kc);
                v.x *= 32.f; v.y *= 32.f; v.z *= 32.f; v.w *= 32.f;
            } else {
                v = *(const float4*)(A + (size_t)s * 1024 + k0 + kc);
            }
            As[kc][row] = v.x; As[kc+1][row] = v.y; As[kc+2][row] = v.z; As[kc+3][row] = v.w;
        }
#pragma unroll
        for (int i = 0; i < 2; i++) {                       // B tile
            int q = tid + i * 256, kr = q >> 5, col = (q & 31) * 4;
            *(float4*)&Bs[kr][col] = *(const float4*)(Bm + (size_t)(k0 + kr) * N + n0 + col);
        }
        __syncthreads();
#pragma unroll
        for (int kk = 0; kk < 16; kk++) {
            float ra[8]; ull rb[4];
            *(float4*)ra       = *(float4*)&As[kk][ty * 8];
            *(float4*)(ra + 4) = *(float4*)&As[kk][ty * 8 + 4];
            float4 b0_ = *(float4*)&Bs[kk][tx * 8];
            float4 b1_ = *(float4*)&Bs[kk][tx * 8 + 4];
            rb[0] = ((ull*)&b0_)[0]; rb[1] = ((ull*)&b0_)[1];
            rb[2] = ((ull*)&b1_)[0]; rb[3] = ((ull*)&b1_)[1];
#pragma unroll
            for (int i = 0; i < 8; i++) {
                ull a2 = dupf(ra[i]);
                FMA2(acc[i][0], a2, rb[0]); FMA2(acc[i][1], a2, rb[1]);
                FMA2(acc[i][2], a2, rb[2]); FMA2(acc[i][3], a2, rb[3]);
            }
        }
        __syncthreads();
    }
    float bi[8];
#pragma unroll
    for (int j = 0; j < 8; j++) bi[j] = bias[n0 + tx * 8 + j];
#pragma unroll
    for (int i = 0; i < 8; i++) {
        int s = m0 + ty * 8 + i;
        size_t off = cmode
            ? (size_t)(s & 15) * 8192000u + (size_t)(s >> 4) * 32000u + n0 + tx * 8
            : (size_t)s * N + n0 + tx * 8;
        float c_[8];
#pragma unroll
        for (int jp = 0; jp < 4; jp++) {
            float2 v = u2f(acc[i][jp]);
            c_[jp*2] = v.x + bi[jp*2]; c_[jp*2+1] = v.y + bi[jp*2+1];
        }
        *(float4*)(C + off)     = *(float4*)c_;
        *(float4*)(C + off + 4) = *(float4*)(c_ + 4);
    }
}

__device__ __forceinline__ void gbar() {
    __syncthreads();
    if (threadIdx.x == 0) {
        __threadfence();
        unsigned gen = *(volatile unsigned*)&g_gen;
        if (atomicAdd(&g_cnt, 1u) == 127u) {
            g_cnt = 0u;
            __threadfence();
            atomicAdd(&g_gen, 1u);
        } else {
            while (*(volatile unsigned*)&g_gen == gen) { }
        }
        __threadfence();
    }
    __syncthreads();
}

// Persistent layer: 128 blocks x 128 threads, all 256 steps.
// Phase A: block (jc=bl%32, kc=bl/32): thread (jj=tid>>2, bg=tid&3)
//   computes z-partials for j=jc*32+jj, b=bg*4..+3, k in [kc*256,+256).
// Phase B: thread gi owns (b=gi>>10, j=gi&1023); c in register across steps.
__global__ __launch_bounds__(128, 1)
void lstm_layer(const float4* __restrict__ Up, const float* __restrict__ XW,
                float* __restrict__ H)
{
    __shared__ float hs[256][20];    // [k][b], pad 20 (16B-aligned rows)
    const int tid = threadIdx.x, bl = blockIdx.x;
    const int jc = bl & 31, kc = bl >> 5, k0 = kc * 256;
    const int jj = tid >> 2, bg = tid & 3;
    const int j  = jc * 32 + jj;
    const int gi = bl * 128 + tid, bB = gi >> 10, jB = gi & 1023;

    // init h buffer 0 and c
    g_h[0][gi] = 0.f;
    float creg = 0.f;
    gbar();

    for (int t = 0; t < 256; t++) {
        const float* hsrc = g_h[t & 1];
        // stage h[16][k0..k0+255] transposed
#pragma unroll
        for (int r = 0; r < 8; r++) {
            int idx = r * 128 + tid, b = idx >> 6, q = idx & 63;
            float4 v = __ldcg((const float4*)(hsrc + b * 1024 + k0) + q);
            hs[q*4+0][b] = v.x; hs[q*4+1][b] = v.y; hs[q*4+2][b] = v.z; hs[q*4+3][b] = v.w;
        }
        __syncthreads();
        // phase A: dot over 256 k
        ull acc[4][2];
#pragma unroll
        for (int g = 0; g < 4; g++) { acc[g][0] = 0ull; acc[g][1] = 0ull; }
        const float4* up = Up + (size_t)k0 * 1024 + j;
        for (int kk = 0; kk < 256; kk++) {
            float4 u = up[(size_t)kk * 1024];
            float4 hv = *(float4*)&hs[kk][bg * 4];
            ull h2a = ((ull*)&hv)[0], h2b = ((ull*)&hv)[1];
            ull a0 = dupf(u.x), a1 = dupf(u.y), a2 = dupf(u.z), a3 = dupf(u.w);
            FMA2(acc[0][0], a0, h2a); FMA2(acc[0][1], a0, h2b);
            FMA2(acc[1][0], a1, h2a); FMA2(acc[1][1], a1, h2b);
            FMA2(acc[2][0], a2, h2a); FMA2(acc[2][1], a2, h2b);
            FMA2(acc[3][0], a3, h2a); FMA2(acc[3][1], a3, h2b);
        }
#pragma unroll
        for (int g = 0; g < 4; g++) {
            float2 v0 = u2f(acc[g][0]), v1 = u2f(acc[g][1]);
            int base = kc * 65536 + g * 1024 + j;
            g_Zp[base + (bg*4+0) * 4096] = v0.x;
            g_Zp[base + (bg*4+1) * 4096] = v0.y;
            g_Zp[base + (bg*4+2) * 4096] = v1.x;
            g_Zp[base + (bg*4+3) * 4096] = v1.y;
        }
        gbar();
        // phase B: reduce + gates
        int s = t * 16 + bB;
        float z[4];
#pragma unroll
        for (int g = 0; g < 4; g++) {
            int col = g * 1024 + jB;
            float v = XW[(size_t)s * 4096 + col];
#pragma unroll
            for (int p = 0; p < 4; p++) v += __ldcg(&g_Zp[p * 65536 + bB * 4096 + col]);
            z[g] = v;
        }
        float i_ = 1.f / (1.f + expf(-z[0]));
        float f_ = 1.f / (1.f + expf(-z[1]));
        float o_ = 1.f / (1.f + expf(-z[3]));
        creg = f_ * creg + i_ * tanhf(z[2]);
        float hn = o_ * tanhf(creg);
        g_h[(t + 1) & 1][bB * 1024 + jB] = hn;
        H[(size_t)s * 1024 + jB] = hn;
        gbar();
    }
}

extern "C" void kernel_launch(void* const* d_in, const int* in_sizes, int n_in,
                              void* d_out, int out_size)
{
    const int*   seq  = (const int*)  d_in[0];
    const float* emb  = (const float*)d_in[1];
    const float* W0   = (const float*)d_in[2];
    const float* U0   = (const float*)d_in[3];
    const float* b0   = (const float*)d_in[4];
    const float* W1   = (const float*)d_in[5];
    const float* U1   = (const float*)d_in[6];
    const float* b1   = (const float*)d_in[7];
    const float* Wout = (const float*)d_in[8];
    const float* bout = (const float*)d_in[9];
    float* out = (float*)d_out;

    float *XW, *H, *Up0, *Up1;
    cudaGetSymbolAddress((void**)&XW,  g_XW);
    cudaGetSymbolAddress((void**)&H,   g_H);
    cudaGetSymbolAddress((void**)&Up0, g_Up0);
    cudaGetSymbolAddress((void**)&Up1, g_Up1);

    repack<<<4096, 256>>>(U0, Up0);
    repack<<<4096, 256>>>(U1, Up1);
    gemm<<<dim3(32, 32), 256>>>(nullptr, W0, b0, XW, 4096, 1, 0, seq, emb);
    lstm_layer<<<128, 128>>>((const float4*)Up0, XW, H);
    gemm<<<dim3(32, 32), 256>>>(H, W1, b1, XW, 4096, 0, 0, nullptr, nullptr);
    lstm_layer<<<128, 128>>>((const float4*)Up1, XW, H);
    gemm<<<dim3(250, 32), 256>>>(H, Wout, bout, out, 32000, 0, 1, nullptr, nullptr);
}

// round 8
// speedup vs baseline: 1.0129x; 1.0129x over previous
#include <cuda_runtime.h>
#include <cuda_bf16.h>
#include <math.h>
#include <stdint.h>

typedef unsigned long long ull;
#define FMA2(acc, a, b) asm("fma.rn.f32x2 %0, %1, %2, %0;" : "+l"(acc) : "l"(a), "l"(b))
__device__ __forceinline__ ull dupf(float x) { ull r; asm("mov.b64 %0, {%1, %1};" : "=l"(r) : "f"(x)); return r; }
__device__ __forceinline__ float2 u2f(ull v) { float2 r; asm("mov.b64 {%0, %1}, %2;" : "=f"(r.x), "=f"(r.y) : "l"(v)); return r; }

// ------------------------- device-global scratch ---------------------------
__device__ float g_XW [(size_t)4096 * 4096];
__device__ float g_H  [(size_t)4096 * 1024];
__device__ float g_Up0[(size_t)1024 * 4096];
__device__ float g_Up1[(size_t)1024 * 4096];
__device__ float g_Zp [4 * 16 * 4096];
__device__ float g_h  [2][16 * 1024];
__device__ unsigned g_cnt, g_gen;

// Up[k][j][g] = U[k][g*1024+j]
__global__ void repack(const float* __restrict__ U, float* __restrict__ Up) {
    int i = blockIdx.x * 256 + threadIdx.x;
    int k = i >> 10, j = i & 1023;
    float4 v = { U[(size_t)k*4096 + j],        U[(size_t)k*4096 + 1024 + j],
                 U[(size_t)k*4096 + 2048 + j], U[(size_t)k*4096 + 3072 + j] };
    ((float4*)Up)[(size_t)k*1024 + j] = v;
}

// --------------------------- f32x2 GEMM -------------------------------------
// C[4096, N] = A @ Bm[1024, N] + bias.  128x128x16 tiles, 8x8/thr via FFMA2.
// amode1: row s <- emb[seq[s%16, s/16]]*32.
// cmode1: row s -> out[(s%16)*256 + s/16] (the [T*16 -> B,T] remap).
__global__ __launch_bounds__(256, 2)
void gemm(const float* __restrict__ A, const float* __restrict__ Bm,
          const float* __restrict__ bias, float* __restrict__ C,
          int N, int amode, int cmode,
          const int* __restrict__ seq, const float* __restrict__ emb)
{
    __shared__ float As[16][128];
    __shared__ float Bs[16][128];
    int tid = threadIdx.x;
    int m0 = blockIdx.y * 128, n0 = blockIdx.x * 128;
    int ty = tid >> 4, tx = tid & 15;
    ull acc[8][4];
#pragma unroll
    for (int i = 0; i < 8; i++)
#pragma unroll
        for (int j = 0; j < 4; j++) acc[i][j] = 0ull;

    for (int k0 = 0; k0 < 1024; k0 += 16) {
#pragma unroll
        for (int i = 0; i < 2; i++) {                        // A tile, transposed
            int q = tid + i * 256, row = q >> 2, kc = (q & 3) * 4, s = m0 + row;
            float4 v;
            if (amode) {
                int tok = seq[(s & 15) * 256 + (s >> 4)];
                v = *(const float4*)(emb + (size_t)tok * 1024 + k0 + kc);
                v.x *= 32.f; v.y *= 32.f; v.z *= 32.f; v.w *= 32.f;
            } else {
                v = *(const float4*)(A + (size_t)s * 1024 + k0 + kc);
            }
            As[kc][row] = v.x; As[kc+1][row] = v.y; As[kc+2][row] = v.z; As[kc+3][row] = v.w;
        }
#pragma unroll
        for (int i = 0; i < 2; i++) {                        // B tile
            int q = tid + i * 256, kr = q >> 5, col = (q & 31) * 4;
            *(float4*)&Bs[kr][col] = *(const float4*)(Bm + (size_t)(k0 + kr) * N + n0 + col);
        }
        __syncthreads();
#pragma unroll
        for (int kk = 0; kk < 16; kk++) {
            float ra[8]; ull rb[4];
            *(float4*)ra       = *(float4*)&As[kk][ty * 8];
            *(float4*)(ra + 4) = *(float4*)&As[kk][ty * 8 + 4];
            float4 b0_ = *(float4*)&Bs[kk][tx * 8];
            float4 b1_ = *(float4*)&Bs[kk][tx * 8 + 4];
            rb[0] = ((ull*)&b0_)[0]; rb[1] = ((ull*)&b0_)[1];
            rb[2] = ((ull*)&b1_)[0]; rb[3] = ((ull*)&b1_)[1];
#pragma unroll
            for (int i = 0; i < 8; i++) {
                ull a2 = dupf(ra[i]);
                FMA2(acc[i][0], a2, rb[0]); FMA2(acc[i][1], a2, rb[1]);
                FMA2(acc[i][2], a2, rb[2]); FMA2(acc[i][3], a2, rb[3]);
            }
        }
        __syncthreads();
    }
    float bi[8];
#pragma unroll
    for (int j = 0; j < 8; j++) bi[j] = bias[n0 + tx * 8 + j];
#pragma unroll
    for (int i = 0; i < 8; i++) {
        int s = m0 + ty * 8 + i;
        size_t off = cmode
            ? (size_t)(s & 15) * 8192000u + (size_t)(s >> 4) * 32000u + n0 + tx * 8
            : (size_t)s * N + n0 + tx * 8;
        float c_[8];
#pragma unroll
        for (int jp = 0; jp < 4; jp++) {
            float2 v = u2f(acc[i][jp]);
            c_[jp*2] = v.x + bi[jp*2]; c_[jp*2+1] = v.y + bi[jp*2+1];
        }
        *(float4*)(C + off)     = *(float4*)c_;
        *(float4*)(C + off + 4) = *(float4*)(c_ + 4);
    }
}

// ------------------- grid barrier WITHOUT L1D flush -------------------------
// release/acquire only on the flag: no gpu-scope generic fence, so ptxas emits
// no CCTL.IVALL and per-block U slices stay L1-resident across steps.
// Cross-block data (g_h, g_Zp) is accessed with ld.cg (L2) on the read side.
#define NBLK 128u
__device__ __forceinline__ void gbar() {
    __syncthreads();
    if (threadIdx.x == 0) {
        unsigned gen, a;
        asm volatile("ld.acquire.gpu.global.u32 %0, [%1];" : "=r"(gen) : "l"(&g_gen));
        asm volatile("atom.release.gpu.global.add.u32 %0, [%1], %2;"
                     : "=r"(a) : "l"(&g_cnt), "r"(1u));
        if (a == NBLK - 1u) {
            asm volatile("st.relaxed.gpu.global.u32 [%0], %1;" :: "l"(&g_cnt), "r"(0u));
            asm volatile("red.release.gpu.global.add.u32 [%0], %1;" :: "l"(&g_gen), "r"(1u));
        } else {
            unsigned c;
            do { asm volatile("ld.acquire.gpu.global.u32 %0, [%1];" : "=r"(c) : "l"(&g_gen)); }
            while (c == gen);
        }
    }
    __syncthreads();
}

// ----------------------- persistent LSTM layer ------------------------------
// 128 blocks x 128 threads. Phase A: block (jc=bl%32, kc=bl/32) computes
// z-partials for 32 j-columns x 16 b over k-chunk [kc*256, +256).
// Phase B: thread gi owns (b, j); c lives in a register across all 256 steps.
__global__ __launch_bounds__(128, 1)
void lstm_layer(const float4* __restrict__ Up, const float* __restrict__ XW,
                float* __restrict__ H)
{
    __shared__ float hs[256][20];
    const int tid = threadIdx.x, bl = blockIdx.x;
    const int jc = bl & 31, kc = bl >> 5, k0 = kc * 256;
    const int jj = tid >> 2, bg = tid & 3;
    const int j  = jc * 32 + jj;
    const int gi = bl * 128 + tid, bB = gi >> 10, jB = gi & 1023;

    g_h[0][gi] = 0.f;
    float creg = 0.f;
    gbar();

    for (int t = 0; t < 256; t++) {
        const float* hsrc = g_h[t & 1];
#pragma unroll
        for (int r = 0; r < 8; r++) {
            int idx = r * 128 + tid, b = idx >> 6, q = idx & 63;
            float4 v = __ldcg((const float4*)(hsrc + b * 1024 + k0) + q);
            hs[q*4+0][b] = v.x; hs[q*4+1][b] = v.y; hs[q*4+2][b] = v.z; hs[q*4+3][b] = v.w;
        }
        __syncthreads();
        ull acc[4][2];
#pragma unroll
        for (int g = 0; g < 4; g++) { acc[g][0] = 0ull; acc[g][1] = 0ull; }
        const float4* up = Up + (size_t)k0 * 1024 + j;
#pragma unroll 8
        for (int kk = 0; kk < 256; kk++) {
            float4 u = up[(size_t)kk * 1024];
            float4 hv = *(float4*)&hs[kk][bg * 4];
            ull h2a = ((ull*)&hv)[0], h2b = ((ull*)&hv)[1];
            ull a0 = dupf(u.x), a1 = dupf(u.y), a2 = dupf(u.z), a3 = dupf(u.w);
            FMA2(acc[0][0], a0, h2a); FMA2(acc[0][1], a0, h2b);
            FMA2(acc[1][0], a1, h2a); FMA2(acc[1][1], a1, h2b);
            FMA2(acc[2][0], a2, h2a); FMA2(acc[2][1], a2, h2b);
            FMA2(acc[3][0], a3, h2a); FMA2(acc[3][1], a3, h2b);
        }
#pragma unroll
        for (int g = 0; g < 4; g++) {
            float2 v0 = u2f(acc[g][0]), v1 = u2f(acc[g][1]);
            int base = kc * 65536 + g * 1024 + j;
            g_Zp[base + (bg*4+0) * 4096] = v0.x;
            g_Zp[base + (bg*4+1) * 4096] = v0.y;
            g_Zp[base + (bg*4+2) * 4096] = v1.x;
            g_Zp[base + (bg*4+3) * 4096] = v1.y;
        }
        gbar();
        int s = t * 16 + bB;
        float z[4];
#pragma unroll
        for (int g = 0; g < 4; g++) {
            int col = g * 1024 + jB;
            float v = XW[(size_t)s * 4096 + col];
#pragma unroll
            for (int p = 0; p < 4; p++) v += __ldcg(&g_Zp[p * 65536 + bB * 4096 + col]);
            z[g] = v;
        }
        float i_ = 1.f / (1.f + expf(-z[0]));
        float f_ = 1.f / (1.f + expf(-z[1]));
        float o_ = 1.f / (1.f + expf(-z[3]));
        creg = f_ * creg + i_ * tanhf(z[2]);
        float hn = o_ * tanhf(creg);
        g_h[(t + 1) & 1][bB * 1024 + jB] = hn;
        H[(size_t)s * 1024 + jB] = hn;
        gbar();
    }
}

// ---------------------------------------------------------------------------
extern "C" void kernel_launch(void* const* d_in, const int* in_sizes, int n_in,
                              void* d_out, int out_size)
{
    const int*   seq  = (const int*)  d_in[0];
    const float* emb  = (const float*)d_in[1];
    const float* W0   = (const float*)d_in[2];
    const float* U0   = (const float*)d_in[3];
    const float* b0   = (const float*)d_in[4];
    const float* W1   = (const float*)d_in[5];
    const float* U1   = (const float*)d_in[6];
    const float* b1   = (const float*)d_in[7];
    const float* Wout = (const float*)d_in[8];
    const float* bout = (const float*)d_in[9];
    float* out = (float*)d_out;

    float *XW, *H, *Up0, *Up1;
    cudaGetSymbolAddress((void**)&XW,  g_XW);
    cudaGetSymbolAddress((void**)&H,   g_H);
    cudaGetSymbolAddress((void**)&Up0, g_Up0);
    cudaGetSymbolAddress((void**)&Up1, g_Up1);

    repack<<<4096, 256>>>(U0, Up0);
    repack<<<4096, 256>>>(U1, Up1);

    gemm<<<dim3(32, 32), 256>>>(nullptr, W0, b0, XW, 4096, 1, 0, seq, emb);
    lstm_layer<<<128, 128>>>((const float4*)Up0, XW, H);
    gemm<<<dim3(32, 32), 256>>>(H, W1, b1, XW, 4096, 0, 0, nullptr, nullptr);
    lstm_layer<<<128, 128>>>((const float4*)Up1, XW, H);
    gemm<<<dim3(250, 32), 256>>>(H, Wout, bout, out, 32000, 0, 1, nullptr, nullptr);
}

// round 9
// speedup vs baseline: 1.2084x; 1.1930x over previous
#include <cuda_runtime.h>
#include <cuda_bf16.h>
#include <math.h>
#include <stdint.h>

typedef unsigned long long ull;
#define FMA2(acc, a, b) asm("fma.rn.f32x2 %0, %1, %2, %0;" : "+l"(acc) : "l"(a), "l"(b))
__device__ __forceinline__ ull dupf(float x) { ull r; asm("mov.b64 %0, {%1, %1};" : "=l"(r) : "f"(x)); return r; }
__device__ __forceinline__ float2 u2f(ull v) { float2 r; asm("mov.b64 {%0, %1}, %2;" : "=f"(r.x), "=f"(r.y) : "l"(v)); return r; }

// ------------------------- device-global scratch ---------------------------
__device__ float g_XW [(size_t)4096 * 4096];
__device__ float g_H  [(size_t)4096 * 1024];
__device__ float g_Up0[(size_t)1024 * 4096];
__device__ float g_Up1[(size_t)1024 * 4096];
__device__ float g_Zp [4 * 16 * 4096];
__device__ float g_h  [2][16 * 1024];
__device__ unsigned g_cnt, g_gen;

// Up[k][j][g] = U[k][g*1024+j]
__global__ void repack(const float* __restrict__ U, float* __restrict__ Up) {
    int i = blockIdx.x * 256 + threadIdx.x;
    int k = i >> 10, j = i & 1023;
    float4 v = { U[(size_t)k*4096 + j],        U[(size_t)k*4096 + 1024 + j],
                 U[(size_t)k*4096 + 2048 + j], U[(size_t)k*4096 + 3072 + j] };
    ((float4*)Up)[(size_t)k*1024 + j] = v;
}

// --------------------------- f32x2 GEMM -------------------------------------
// C[4096, N] = A @ Bm[1024, N] + bias.  128x128x16 tiles, 8x8/thr via FFMA2.
// grid: (x = m-tiles [32], y = n-tiles) so concurrent waves share B-panels and
// the 16MB A operand stays L2-resident.
// amode1: row s <- emb[seq[s%16, s/16]]*32.
// cmode1: row s -> out[(s%16)*256 + s/16] (the [T*16 -> B,T] remap).
__global__ __launch_bounds__(256, 2)
void gemm(const float* __restrict__ A, const float* __restrict__ Bm,
          const float* __restrict__ bias, float* __restrict__ C,
          int N, int amode, int cmode,
          const int* __restrict__ seq, const float* __restrict__ emb)
{
    __shared__ float As[16][128];
    __shared__ float Bs[16][128];
    int tid = threadIdx.x;
    int m0 = blockIdx.x * 128, n0 = blockIdx.y * 128;
    int ty = tid >> 4, tx = tid & 15;
    ull acc[8][4];
#pragma unroll
    for (int i = 0; i < 8; i++)
#pragma unroll
        for (int j = 0; j < 4; j++) acc[i][j] = 0ull;

    for (int k0 = 0; k0 < 1024; k0 += 16) {
#pragma unroll
        for (int i = 0; i < 2; i++) {                        // A tile, transposed
            int q = tid + i * 256, row = q >> 2, kc = (q & 3) * 4, s = m0 + row;
            float4 v;
            if (amode) {
                int tok = seq[(s & 15) * 256 + (s >> 4)];
                v = *(const float4*)(emb + (size_t)tok * 1024 + k0 + kc);
                v.x *= 32.f; v.y *= 32.f; v.z *= 32.f; v.w *= 32.f;
            } else {
                v = *(const float4*)(A + (size_t)s * 1024 + k0 + kc);
            }
            As[kc][row] = v.x; As[kc+1][row] = v.y; As[kc+2][row] = v.z; As[kc+3][row] = v.w;
        }
#pragma unroll
        for (int i = 0; i < 2; i++) {                        // B tile
            int q = tid + i * 256, kr = q >> 5, col = (q & 31) * 4;
            *(float4*)&Bs[kr][col] = *(const float4*)(Bm + (size_t)(k0 + kr) * N + n0 + col);
        }
        __syncthreads();
#pragma unroll
        for (int kk = 0; kk < 16; kk++) {
            float ra[8]; ull rb[4];
            *(float4*)ra       = *(float4*)&As[kk][ty * 8];
            *(float4*)(ra + 4) = *(float4*)&As[kk][ty * 8 + 4];
            float4 b0_ = *(float4*)&Bs[kk][tx * 8];
            float4 b1_ = *(float4*)&Bs[kk][tx * 8 + 4];
            rb[0] = ((ull*)&b0_)[0]; rb[1] = ((ull*)&b0_)[1];
            rb[2] = ((ull*)&b1_)[0]; rb[3] = ((ull*)&b1_)[1];
#pragma unroll
            for (int i = 0; i < 8; i++) {
                ull a2 = dupf(ra[i]);
                FMA2(acc[i][0], a2, rb[0]); FMA2(acc[i][1], a2, rb[1]);
                FMA2(acc[i][2], a2, rb[2]); FMA2(acc[i][3], a2, rb[3]);
            }
        }
        __syncthreads();
    }
    float bi[8];
#pragma unroll
    for (int j = 0; j < 8; j++) bi[j] = bias[n0 + tx * 8 + j];
#pragma unroll
    for (int i = 0; i < 8; i++) {
        int s = m0 + ty * 8 + i;
        size_t off = cmode
            ? (size_t)(s & 15) * 8192000u + (size_t)(s >> 4) * 32000u + n0 + tx * 8
            : (size_t)s * N + n0 + tx * 8;
        float c_[8];
#pragma unroll
        for (int jp = 0; jp < 4; jp++) {
            float2 v = u2f(acc[i][jp]);
            c_[jp*2] = v.x + bi[jp*2]; c_[jp*2+1] = v.y + bi[jp*2+1];
        }
        *(float4*)(C + off)     = *(float4*)c_;
        *(float4*)(C + off + 4) = *(float4*)(c_ + 4);
    }
}

// ----------------------------- grid barrier ---------------------------------
#define NBLK 128u
__device__ __forceinline__ void gbar() {
    __syncthreads();
    if (threadIdx.x == 0) {
        unsigned gen, a;
        asm volatile("ld.acquire.gpu.global.u32 %0, [%1];" : "=r"(gen) : "l"(&g_gen));
        asm volatile("atom.release.gpu.global.add.u32 %0, [%1], %2;"
                     : "=r"(a) : "l"(&g_cnt), "r"(1u));
        if (a == NBLK - 1u) {
            asm volatile("st.relaxed.gpu.global.u32 [%0], %1;" :: "l"(&g_cnt), "r"(0u));
            asm volatile("red.release.gpu.global.add.u32 [%0], %1;" :: "l"(&g_gen), "r"(1u));
        } else {
            unsigned c;
            do { asm volatile("ld.acquire.gpu.global.u32 %0, [%1];" : "=r"(c) : "l"(&g_gen)); }
            while (c == gen);
        }
    }
    __syncthreads();
}

// ----------------------- persistent LSTM layer ------------------------------
// 128 blocks x 128 threads. The block's 128KB Up slice lives in SHARED memory
// (loaded once), so the barrier's L1 invalidations cannot evict it. Phase A:
// block (jc=bl%32, kc=bl/32) computes z-partials for 32 j x 4 gates x 16 b
// over k-chunk [kc*256, +256). Phase B: thread gi owns (b, j); c in register.
#define SMEM_LSTM (131072 + 256 * 20 * 4)
__global__ __launch_bounds__(128, 1)
void lstm_layer(const float4* __restrict__ Up, const float* __restrict__ XW,
                float* __restrict__ H)
{
    extern __shared__ char sm_[];
    float4* up_s = (float4*)sm_;                          // [256][32] = 128KB
    float (*hs)[20] = (float(*)[20])(sm_ + 131072);       // [256][20] = 20KB

    const int tid = threadIdx.x, bl = blockIdx.x;
    const int jc = bl & 31, kc = bl >> 5, k0 = kc * 256;
    const int jj = tid >> 2, bg = tid & 3;
    const int gi = bl * 128 + tid, bB = gi >> 10, jB = gi & 1023;

    // one-time: stage this block's Up slice into smem
    {
        const float4* up = Up + (size_t)k0 * 1024 + jc * 32;
#pragma unroll 8
        for (int i = tid; i < 8192; i += 128)
            up_s[i] = up[(size_t)(i >> 5) * 1024 + (i & 31)];
    }
    g_h[0][gi] = 0.f;
    float creg = 0.f;
    gbar();

    for (int t = 0; t < 256; t++) {
        const float* hsrc = g_h[t & 1];
#pragma unroll
        for (int r = 0; r < 8; r++) {
            int idx = r * 128 + tid, b = idx >> 6, q = idx & 63;
            float4 v = __ldcg((const float4*)(hsrc + b * 1024 + k0) + q);
            hs[q*4+0][b] = v.x; hs[q*4+1][b] = v.y; hs[q*4+2][b] = v.z; hs[q*4+3][b] = v.w;
        }
        __syncthreads();
        ull acc[4][2];
#pragma unroll
        for (int g = 0; g < 4; g++) { acc[g][0] = 0ull; acc[g][1] = 0ull; }
        const float4* ups = up_s + jj;
#pragma unroll 8
        for (int kk = 0; kk < 256; kk++) {
            float4 u  = ups[kk * 32];
            float4 hv = *(float4*)&hs[kk][bg * 4];
            ull h2a = ((ull*)&hv)[0], h2b = ((ull*)&hv)[1];
            ull a0 = dupf(u.x), a1 = dupf(u.y), a2 = dupf(u.z), a3 = dupf(u.w);
            FMA2(acc[0][0], a0, h2a); FMA2(acc[0][1], a0, h2b);
            FMA2(acc[1][0], a1, h2a); FMA2(acc[1][1], a1, h2b);
            FMA2(acc[2][0], a2, h2a); FMA2(acc[2][1], a2, h2b);
            FMA2(acc[3][0], a3, h2a); FMA2(acc[3][1], a3, h2b);
        }
        const int j = jc * 32 + jj;
#pragma unroll
        for (int g = 0; g < 4; g++) {
            float2 v0 = u2f(acc[g][0]), v1 = u2f(acc[g][1]);
            int base = kc * 65536 + g * 1024 + j;
            g_Zp[base + (bg*4+0) * 4096] = v0.x;
            g_Zp[base + (bg*4+1) * 4096] = v0.y;
            g_Zp[base + (bg*4+2) * 4096] = v1.x;
            g_Zp[base + (bg*4+3) * 4096] = v1.y;
        }
        gbar();
        int s = t * 16 + bB;
        float z[4];
#pragma unroll
        for (int g = 0; g < 4; g++) {
            int col = g * 1024 + jB;
            float v = XW[(size_t)s * 4096 + col];
#pragma unroll
            for (int p = 0; p < 4; p++) v += __ldcg(&g_Zp[p * 65536 + bB * 4096 + col]);
            z[g] = v;
        }
        float i_ = 1.f / (1.f + expf(-z[0]));
        float f_ = 1.f / (1.f + expf(-z[1]));
        float o_ = 1.f / (1.f + expf(-z[3]));
        creg = f_ * creg + i_ * tanhf(z[2]);
        float hn = o_ * tanhf(creg);
        g_h[(t + 1) & 1][bB * 1024 + jB] = hn;
        H[(size_t)s * 1024 + jB] = hn;
        gbar();
    }
}

// ---------------------------------------------------------------------------
extern "C" void kernel_launch(void* const* d_in, const int* in_sizes, int n_in,
                              void* d_out, int out_size)
{
    const int*   seq  = (const int*)  d_in[0];
    const float* emb  = (const float*)d_in[1];
    const float* W0   = (const float*)d_in[2];
    const float* U0   = (const float*)d_in[3];
    const float* b0   = (const float*)d_in[4];
    const float* W1   = (const float*)d_in[5];
    const float* U1   = (const float*)d_in[6];
    const float* b1   = (const float*)d_in[7];
    const float* Wout = (const float*)d_in[8];
    const float* bout = (const float*)d_in[9];
    float* out = (float*)d_out;

    float *XW, *H, *Up0, *Up1;
    cudaGetSymbolAddress((void**)&XW,  g_XW);
    cudaGetSymbolAddress((void**)&H,   g_H);
    cudaGetSymbolAddress((void**)&Up0, g_Up0);
    cudaGetSymbolAddress((void**)&Up1, g_Up1);

    cudaFuncSetAttribute(lstm_layer, cudaFuncAttributeMaxDynamicSharedMemorySize, SMEM_LSTM);

    repack<<<4096, 256>>>(U0, Up0);
    repack<<<4096, 256>>>(U1, Up1);

    gemm<<<dim3(32, 32), 256>>>(nullptr, W0, b0, XW, 4096, 1, 0, seq, emb);
    lstm_layer<<<128, 128, SMEM_LSTM>>>((const float4*)Up0, XW, H);
    gemm<<<dim3(32, 32), 256>>>(H, W1, b1, XW, 4096, 0, 0, nullptr, nullptr);
    lstm_layer<<<128, 128, SMEM_LSTM>>>((const float4*)Up1, XW, H);
    gemm<<<dim3(32, 250), 256>>>(H, Wout, bout, out, 32000, 0, 1, nullptr, nullptr);
}